// round 13
// baseline (speedup 1.0000x reference)
#include <cuda_runtime.h>
#include <cuda_fp16.h>
#include <math.h>
#include <stdint.h>

#define BB     16
#define NN     512
#define DD     1024
#define EE     2048
#define SS     128
#define FF     4224
#define MTOT   8192

// ---------------- scratch ----------------------------------------------------
__device__ __half g_xnh[(size_t)MTOT * DD];
__device__ __half g_xnl[(size_t)MTOT * DD];
__device__ __half g_wuv[(size_t)FF * DD];
__device__ __half g_u  [(size_t)MTOT * EE];      // u gate, fp16
__device__ __half g_vt [(size_t)BB * EE * NN];   // V^T fp16
__device__ __half g_qh [(size_t)MTOT * SS];
__device__ __half g_ql [(size_t)MTOT * SS];
__device__ __half g_kh [(size_t)MTOT * SS];
__device__ __half g_kl [(size_t)MTOT * SS];
__device__ __half g_kerh[(size_t)BB * NN * NN];  // ker single fp16
__device__ __half g_gh [(size_t)MTOT * EE];
__device__ __half g_ow [(size_t)DD * EE];

// ---------------- helpers -----------------------------------------------------
__device__ __forceinline__ uint32_t smem_u32(const void* p) {
    uint32_t a;
    asm("{ .reg .u64 t; cvta.to.shared.u64 t, %1; cvt.u32.u64 %0, t; }" : "=r"(a) : "l"(p));
    return a;
}
__device__ __forceinline__ void ldmx4(uint32_t* r, uint32_t a) {
    asm volatile("ldmatrix.sync.aligned.m8n8.x4.shared.b16 {%0,%1,%2,%3}, [%4];"
        : "=r"(r[0]), "=r"(r[1]), "=r"(r[2]), "=r"(r[3]) : "r"(a));
}
__device__ __forceinline__ void mma16816(float* c, const uint32_t* a,
                                         uint32_t b0, uint32_t b1) {
    asm volatile("mma.sync.aligned.m16n8k16.row.col.f32.f16.f16.f32 "
        "{%0,%1,%2,%3}, {%4,%5,%6,%7}, {%8,%9}, {%0,%1,%2,%3};"
        : "+f"(c[0]), "+f"(c[1]), "+f"(c[2]), "+f"(c[3])
        : "r"(a[0]), "r"(a[1]), "r"(a[2]), "r"(a[3]), "r"(b0), "r"(b1));
}
__device__ __forceinline__ void cp16(uint32_t dst, const void* src) {
    asm volatile("cp.async.cg.shared.global [%0], [%1], 16;" :: "r"(dst), "l"(src) : "memory");
}
#define CP_COMMIT() asm volatile("cp.async.commit_group;" ::: "memory")
#define CP_WAIT1()  asm volatile("cp.async.wait_group 1;"  ::: "memory")
#define CP_WAIT0()  asm volatile("cp.async.wait_group 0;"  ::: "memory")

// load one 128x64(fp16) tile chunk (16 KB) into SW128-swizzled smem, 256 thr
__device__ __forceinline__ void ld_tile(uint32_t dst, const __half* src,
                                        int ld_elem, size_t kb0, int tid) {
    const char* sb = (const char*)src + kb0;
#pragma unroll
    for (int it = 0; it < 4; ++it) {
        int L = tid * 16 + it * 4096;
        int row = L >> 7, kb = L & 127;
        cp16(dst + (L ^ ((L >> 3) & 0x70)),
             sb + (size_t)row * ((size_t)ld_elem * 2) + kb);
    }
}

// ---------------- fp16 split MMA GEMM core (2-stage, R11 form) ------------------
// C = (Ah [+Al]) * (Bh [+Bl])^T ; products: ah*bh [+ al*bh] [+ ah*bl]
// A 128xK fp16 (lda), B 128xK fp16 (ldb). 8 warps 4(M)x2(N), warp 32x64.
// Epilogue f2(row, col, v0, v1) with (col, col+1) pair, tile-relative.
template <bool SPLIT_A, bool SPLIT_B, class F2>
__device__ __forceinline__ void mma_gemm(
    const __half* __restrict__ Ah, const __half* __restrict__ Al, int lda,
    const __half* __restrict__ Bh, const __half* __restrict__ Bl, int ldb,
    int K, F2 f2)
{
    constexpr uint32_t OFFAL = 16384;
    constexpr uint32_t OFFB  = SPLIT_A ? 32768 : 16384;
    constexpr uint32_t OFFBL = OFFB + 16384;
    constexpr uint32_t STG   = 16384u * (2 + (SPLIT_A ? 1 : 0) + (SPLIT_B ? 1 : 0));
    extern __shared__ char smem[];
    const uint32_t sbase = smem_u32(smem);
    const int tid = threadIdx.x;
    const int lane = tid & 31;
    const int wid = tid >> 5;
    const int wm = wid >> 1, wn = wid & 1;

    float c[2][8][4];
#pragma unroll
    for (int i = 0; i < 2; ++i)
#pragma unroll
        for (int j = 0; j < 8; ++j)
#pragma unroll
            for (int e = 0; e < 4; ++e) c[i][j][e] = 0.f;

    const int NCH = K >> 6;
    const int lhalf = (lane >> 4) << 4;
    const int arow  = wm * 32 + (lane & 15);
    const int brow  = wn * 64 + (lane & 15);

#define LOAD_CHUNK(CC, ST)                                                    \
    {                                                                         \
        uint32_t st_ = sbase + (ST) * STG;                                    \
        size_t kb0_ = (size_t)(CC) * 128;                                     \
        ld_tile(st_, Ah, lda, kb0_, tid);                                     \
        if (SPLIT_A) ld_tile(st_ + OFFAL, Al, lda, kb0_, tid);                \
        ld_tile(st_ + OFFB, Bh, ldb, kb0_, tid);                              \
        if (SPLIT_B) ld_tile(st_ + OFFBL, Bl, ldb, kb0_, tid);                \
    }

    LOAD_CHUNK(0, 0); CP_COMMIT();

    for (int cc = 0; cc < NCH; ++cc) {
        if (cc + 1 < NCH) {
            LOAD_CHUNK(cc + 1, (cc + 1) & 1);
            CP_COMMIT();
            CP_WAIT1();
        } else {
            CP_WAIT0();
        }
        __syncthreads();

        const uint32_t st = sbase + (cc & 1) * STG;
#pragma unroll
        for (int ks = 0; ks < 4; ++ks) {
            const int kb = ks * 32 + lhalf;
            uint32_t ah[2][4], al[2][4];
#pragma unroll
            for (int mt = 0; mt < 2; ++mt) {
                uint32_t off = (uint32_t)(arow + mt * 16) * 128 + kb;
                off ^= (off >> 3) & 0x70;
                ldmx4(ah[mt], st + off);
                if (SPLIT_A) ldmx4(al[mt], st + OFFAL + off);
            }
#pragma unroll
            for (int np = 0; np < 4; ++np) {
                uint32_t off = (uint32_t)(brow + np * 16) * 128 + kb;
                off ^= (off >> 3) & 0x70;
                uint32_t bh[4];
                ldmx4(bh, st + OFFB + off);
                uint32_t bl[4];
                if (SPLIT_B) ldmx4(bl, st + OFFBL + off);
#pragma unroll
                for (int mt = 0; mt < 2; ++mt) {
                    float* c0 = c[mt][np * 2 + 0];
                    float* c1 = c[mt][np * 2 + 1];
                    mma16816(c0, ah[mt], bh[0], bh[2]);
                    mma16816(c1, ah[mt], bh[1], bh[3]);
                    if (SPLIT_A) {
                        mma16816(c0, al[mt], bh[0], bh[2]);
                        mma16816(c1, al[mt], bh[1], bh[3]);
                    }
                    if (SPLIT_B) {
                        mma16816(c0, ah[mt], bl[0], bl[2]);
                        mma16816(c1, ah[mt], bl[1], bl[3]);
                    }
                }
            }
        }
        __syncthreads();
    }
#undef LOAD_CHUNK

    const int gID = lane >> 2, tg = lane & 3;
#pragma unroll
    for (int mt = 0; mt < 2; ++mt)
#pragma unroll
        for (int j = 0; j < 8; ++j) {
            int row = wm * 32 + mt * 16 + gID;
            int col = wn * 64 + j * 8 + tg * 2;
            f2(row,     col, c[mt][j][0], c[mt][j][1]);
            f2(row + 8, col, c[mt][j][2], c[mt][j][3]);
        }
}

// split a fp32 pair into hi/lo half2
__device__ __forceinline__ void split2(float v0, float v1,
                                       __half2& h, __half2& l) {
    h.x = __float2half_rn(v0); h.y = __float2half_rn(v1);
    l.x = __float2half_rn(v0 - __half2float(h.x));
    l.y = __float2half_rn(v1 - __half2float(h.y));
}

// ---------------- LayerNorm -> fp16 hi/lo --------------------------------------
__global__ __launch_bounds__(256) void ln_kernel(const float* __restrict__ x,
                                                 const float* __restrict__ w,
                                                 const float* __restrict__ b)
{
    int row = blockIdx.x;
    int tid = threadIdx.x;
    float4 v = ((const float4*)(x + (size_t)row * DD))[tid];
    float s  = v.x + v.y + v.z + v.w;
    float ss = v.x*v.x + v.y*v.y + v.z*v.z + v.w*v.w;
#pragma unroll
    for (int o = 16; o; o >>= 1) {
        s  += __shfl_xor_sync(0xffffffffu, s , o);
        ss += __shfl_xor_sync(0xffffffffu, ss, o);
    }
    __shared__ float sh_s[8], sh_ss[8];
    int warp = tid >> 5;
    if ((tid & 31) == 0) { sh_s[warp] = s; sh_ss[warp] = ss; }
    __syncthreads();
    if (tid == 0) {
        float ts = 0.f, tss = 0.f;
#pragma unroll
        for (int i = 0; i < 8; ++i) { ts += sh_s[i]; tss += sh_ss[i]; }
        sh_s[0] = ts; sh_ss[0] = tss;
    }
    __syncthreads();
    float mean = sh_s[0] * (1.0f / DD);
    float var  = sh_ss[0] * (1.0f / DD) - mean * mean;
    float rs   = rsqrtf(var + 1e-5f);
    float4 wv = ((const float4*)w)[tid];
    float4 bv = ((const float4*)b)[tid];
    float o0 = (v.x - mean) * rs * wv.x + bv.x;
    float o1 = (v.y - mean) * rs * wv.y + bv.y;
    float o2 = (v.z - mean) * rs * wv.z + bv.z;
    float o3 = (v.w - mean) * rs * wv.w + bv.w;
    size_t eb = (size_t)row * DD + tid * 4;
    __half2 hA, lA, hB, lB;
    split2(o0, o1, hA, lA);
    split2(o2, o3, hB, lB);
    ((__half2*)(g_xnh + eb))[0] = hA;
    ((__half2*)(g_xnh + eb))[1] = hB;
    ((__half2*)(g_xnl + eb))[0] = lA;
    ((__half2*)(g_xnl + eb))[1] = lB;
}

// ---------------- fp32 -> fp16 convert ------------------------------------------
__global__ __launch_bounds__(256) void convert_kernel(const float* __restrict__ s,
                                                      __half* __restrict__ d,
                                                      int n4)
{
    int i = blockIdx.x * blockDim.x + threadIdx.x;
    if (i >= n4) return;
    float4 v = ((const float4*)s)[i];
    __half2 a; a.x = __float2half_rn(v.x); a.y = __float2half_rn(v.y);
    __half2 b; b.x = __float2half_rn(v.z); b.y = __float2half_rn(v.w);
    ((__half2*)d)[2 * i]     = a;
    ((__half2*)d)[2 * i + 1] = b;
}

// ---------------- GEMM1a: u,v cols [0,4096), SINGLE product ---------------------
// epilogue routes: col<E -> u (fp16), E<=col<2E -> V^T (fp16)
__global__ __launch_bounds__(256, 2) void gemm_uv_mma(const float* __restrict__ uv_b)
{
    const int m0 = blockIdx.y * 128, n0 = blockIdx.x * 128;
    mma_gemm<false, false>(g_xnh + (size_t)m0 * DD, (const __half*)0, DD,
                           g_wuv + (size_t)n0 * DD, (const __half*)0, DD, DD,
        [&](int r, int cidx, float v0, float v1) {
            int row = m0 + r, col = n0 + cidx;
            float t0 = v0 + uv_b[col];
            float t1 = v1 + uv_b[col + 1];
            float s0 = t0 / (1.f + expf(-t0));
            float s1 = t1 / (1.f + expf(-t1));
            if (col >= EE) {
                int bt = row >> 9, n = row & (NN - 1);
                int e = col - EE;
                size_t base = ((size_t)bt * EE + e) * NN + n;
                g_vt[base]      = __float2half_rn(s0);
                g_vt[base + NN] = __float2half_rn(s1);
            } else {
                __half2 h;
                h.x = __float2half_rn(s0);
                h.y = __float2half_rn(s1);
                *(__half2*)(g_u + (size_t)row * EE + col) = h;
            }
        });
}

// ---------------- GEMM1b: base cols + fused gamma/beta + RoPE -> q,k -------------
// base tile (128 rows x 128 cols) is CTA-resident: stash silu in stage smem,
// then apply RoPE and emit q/k hi/lo directly.
#define BSM_LD 132
__global__ __launch_bounds__(256, 2) void gemm_base_mma(const float* __restrict__ uv_b,
                                                        const float* __restrict__ gamma,
                                                        const float* __restrict__ beta)
{
    extern __shared__ char smem[];
    float* bsm = (float*)smem;   // 128 x BSM_LD fp32 (reuses stage memory)
    const int m0 = blockIdx.y * 128;
    mma_gemm<true, false>(g_xnh + (size_t)m0 * DD, g_xnl + (size_t)m0 * DD, DD,
                          g_wuv + (size_t)(2 * EE) * DD, (const __half*)0, DD, DD,
        [&](int r, int cidx, float v0, float v1) {
            float t0 = v0 + uv_b[2 * EE + cidx];
            float t1 = v1 + uv_b[2 * EE + cidx + 1];
            bsm[r * BSM_LD + cidx]     = t0 / (1.f + expf(-t0));
            bsm[r * BSM_LD + cidx + 1] = t1 / (1.f + expf(-t1));
        });
    __syncthreads();

    const int tid = threadIdx.x;
#pragma unroll
    for (int i = 0; i < 32; ++i) {
        int idx = tid + i * 256;          // 0..8191
        int r = idx >> 6, s = idx & 63;
        int row = m0 + r;
        int n = row & (NN - 1);
        float b1 = bsm[r * BSM_LD + s];
        float b2 = bsm[r * BSM_LD + s + 64];
        float inv_freq = powf(10000.0f, (float)s * (1.0f / 64.0f));
        float arg = (float)n * inv_freq;
        float sn = sinf(arg);
        float cs = cosf(arg);
#pragma unroll
        for (int h = 0; h < 2; ++h) {
            float x1 = b1 * gamma[h * SS + s]      + beta[h * SS + s];
            float x2 = b2 * gamma[h * SS + s + 64] + beta[h * SS + s + 64];
            float q1 = x1 * cs - x2 * sn;
            float q2 = x2 * cs + x1 * sn;
            __half* dh = (h == 0 ? g_qh : g_kh) + (size_t)row * SS;
            __half* dl = (h == 0 ? g_ql : g_kl) + (size_t)row * SS;
            __half h1 = __float2half_rn(q1), h2 = __float2half_rn(q2);
            dh[s]      = h1;
            dh[s + 64] = h2;
            dl[s]      = __float2half_rn(q1 - __half2float(h1));
            dl[s + 64] = __float2half_rn(q2 - __half2float(h2));
        }
    }
}

// ---------------- qk: 3-product split MMA + bias + relu^2 -> ker (single fp16) ---
__global__ __launch_bounds__(256) void qk_mma(const float* __restrict__ w_rel)
{
    const int bt = blockIdx.z;
    const int m0 = blockIdx.y * 128, n0 = blockIdx.x * 128;
    const size_t rbase = (size_t)bt * NN;
    mma_gemm<true, true>(g_qh + (rbase + m0) * SS, g_ql + (rbase + m0) * SS, SS,
                         g_kh + (rbase + n0) * SS, g_kl + (rbase + n0) * SS, SS, SS,
        [&](int r, int cidx, float v0, float v1) {
            int row = m0 + r, col = n0 + cidx;
            float t0 = v0 * (1.0f / 512.0f) + w_rel[col - row + 511];
            float t1 = v1 * (1.0f / 512.0f) + w_rel[col + 1 - row + 511];
            float r0 = fmaxf(t0, 0.f), r1 = fmaxf(t1, 0.f);
            __half2 h;
            h.x = __float2half_rn(r0 * r0);
            h.y = __float2half_rn(r1 * r1);
            *(__half2*)(g_kerh + (rbase + row) * NN + col) = h;
        });
}

// ---------------- kv: g = (ker @ V) * u  (single product) ------------------------
__global__ __launch_bounds__(256, 2) void kv_mma()
{
    const int bt = blockIdx.z;
    const int m0 = blockIdx.y * 128, n0 = blockIdx.x * 128;
    const size_t rbase = (size_t)bt * NN;
    mma_gemm<false, false>(g_kerh + (rbase + m0) * NN, (const __half*)0, NN,
                           g_vt + ((size_t)bt * EE + n0) * NN, (const __half*)0, NN, NN,
        [&](int r, int cidx, float v0, float v1) {
            size_t grow = rbase + m0 + r;
            int col = n0 + cidx;
            __half2 u2 = *(const __half2*)(g_u + grow * EE + col);
            __half2 h;
            h.x = __float2half_rn(__half2float(u2.x) * v0);
            h.y = __float2half_rn(__half2float(u2.y) * v1);
            *(__half2*)(g_gh + grow * EE + col) = h;
        });
}

// ---------------- out = g @ o_w^T + o_b + shortcut (single product) ---------------
__global__ __launch_bounds__(256, 2) void out_mma(const float* __restrict__ o_b,
                                                  const float* __restrict__ x,
                                                  float* __restrict__ out)
{
    const int m0 = blockIdx.y * 128, n0 = blockIdx.x * 128;
    mma_gemm<false, false>(g_gh + (size_t)m0 * EE, (const __half*)0, EE,
                           g_ow + (size_t)n0 * EE, (const __half*)0, EE, EE,
        [&](int r, int cidx, float v0, float v1) {
            int row = m0 + r, col = n0 + cidx;
            float2 xr = *(const float2*)(x + (size_t)row * DD + col);
            float2 o;
            o.x = v0 + o_b[col]     + xr.x;
            o.y = v1 + o_b[col + 1] + xr.y;
            *(float2*)(out + (size_t)row * DD + col) = o;
        });
}

// ---------------- launch ------------------------------------------------------------
#define SMEM_UV   (2 * 32768)   // single product: A|B
#define SMEM_BASE (2 * 49152)   // A-split (also holds 128x132 fp32 = 67.6 KB epilogue)
#define SMEM_QK   (2 * 65536)   // both split
#define SMEM_KV   (2 * 32768)
#define SMEM_OUT  (2 * 32768)

extern "C" void kernel_launch(void* const* d_in, const int* in_sizes, int n_in,
                              void* d_out, int out_size)
{
    const float* x     = (const float*)d_in[0];
    const float* ln_w  = (const float*)d_in[1];
    const float* ln_b  = (const float*)d_in[2];
    const float* uv_w  = (const float*)d_in[3];
    const float* uv_b  = (const float*)d_in[4];
    const float* gamma = (const float*)d_in[5];
    const float* beta  = (const float*)d_in[6];
    const float* o_w   = (const float*)d_in[7];
    const float* o_b   = (const float*)d_in[8];
    const float* w_rel = (const float*)d_in[9];
    float* out = (float*)d_out;

    cudaFuncSetAttribute(gemm_uv_mma,   cudaFuncAttributeMaxDynamicSharedMemorySize, SMEM_UV);
    cudaFuncSetAttribute(gemm_base_mma, cudaFuncAttributeMaxDynamicSharedMemorySize, SMEM_BASE);
    cudaFuncSetAttribute(kv_mma,        cudaFuncAttributeMaxDynamicSharedMemorySize, SMEM_KV);
    cudaFuncSetAttribute(out_mma,       cudaFuncAttributeMaxDynamicSharedMemorySize, SMEM_OUT);
    cudaFuncSetAttribute(qk_mma,        cudaFuncAttributeMaxDynamicSharedMemorySize, SMEM_QK);

    __half *wuv, *ow;
    cudaGetSymbolAddress((void**)&wuv, g_wuv);
    cudaGetSymbolAddress((void**)&ow,  g_ow);

    ln_kernel<<<MTOT, 256>>>(x, ln_w, ln_b);
    convert_kernel<<<(FF * DD / 4 + 255) / 256, 256>>>(uv_w, wuv, FF * DD / 4);
    convert_kernel<<<(DD * EE / 4 + 255) / 256, 256>>>(o_w, ow, DD * EE / 4);
    gemm_uv_mma  <<<dim3(4096 / 128, MTOT / 128), 256, SMEM_UV>>>(uv_b);
    gemm_base_mma<<<dim3(1,          MTOT / 128), 256, SMEM_BASE>>>(uv_b, gamma, beta);
    qk_mma<<<dim3(NN / 128, NN / 128, BB), 256, SMEM_QK>>>(w_rel);
    kv_mma<<<dim3(EE / 128, NN / 128, BB), 256, SMEM_KV>>>();
    out_mma<<<dim3(DD / 128, MTOT / 128), 256, SMEM_OUT>>>(o_b, x, out);
}

// round 14
// speedup vs baseline: 1.0549x; 1.0549x over previous
#include <cuda_runtime.h>
#include <cuda_fp16.h>
#include <math.h>
#include <stdint.h>

#define BB     16
#define NN     512
#define DD     1024
#define EE     2048
#define SS     128
#define FF     4224
#define MTOT   8192

// ---------------- scratch ----------------------------------------------------
__device__ __half g_xnh[(size_t)MTOT * DD];
__device__ __half g_xnl[(size_t)MTOT * DD];
__device__ __half g_wuv[(size_t)FF * DD];
__device__ __half g_u  [(size_t)MTOT * EE];      // u gate, fp16
__device__ float  g_base[(size_t)MTOT * SS];     // base (pre-RoPE), fp32 dense
__device__ __half g_vt [(size_t)BB * EE * NN];   // V^T fp16
__device__ __half g_qh [(size_t)MTOT * SS];
__device__ __half g_ql [(size_t)MTOT * SS];
__device__ __half g_kh [(size_t)MTOT * SS];
__device__ __half g_kl [(size_t)MTOT * SS];
__device__ __half g_kerh[(size_t)BB * NN * NN];  // ker single fp16
__device__ __half g_gh [(size_t)MTOT * EE];
__device__ __half g_ow [(size_t)DD * EE];

// ---------------- helpers -----------------------------------------------------
__device__ __forceinline__ uint32_t smem_u32(const void* p) {
    uint32_t a;
    asm("{ .reg .u64 t; cvta.to.shared.u64 t, %1; cvt.u32.u64 %0, t; }" : "=r"(a) : "l"(p));
    return a;
}
__device__ __forceinline__ void ldmx4(uint32_t* r, uint32_t a) {
    asm volatile("ldmatrix.sync.aligned.m8n8.x4.shared.b16 {%0,%1,%2,%3}, [%4];"
        : "=r"(r[0]), "=r"(r[1]), "=r"(r[2]), "=r"(r[3]) : "r"(a));
}
__device__ __forceinline__ void mma16816(float* c, const uint32_t* a,
                                         uint32_t b0, uint32_t b1) {
    asm volatile("mma.sync.aligned.m16n8k16.row.col.f32.f16.f16.f32 "
        "{%0,%1,%2,%3}, {%4,%5,%6,%7}, {%8,%9}, {%0,%1,%2,%3};"
        : "+f"(c[0]), "+f"(c[1]), "+f"(c[2]), "+f"(c[3])
        : "r"(a[0]), "r"(a[1]), "r"(a[2]), "r"(a[3]), "r"(b0), "r"(b1));
}
__device__ __forceinline__ void cp16(uint32_t dst, const void* src) {
    asm volatile("cp.async.cg.shared.global [%0], [%1], 16;" :: "r"(dst), "l"(src) : "memory");
}
#define CP_COMMIT() asm volatile("cp.async.commit_group;" ::: "memory")
#define CP_WAIT1()  asm volatile("cp.async.wait_group 1;"  ::: "memory")
#define CP_WAIT0()  asm volatile("cp.async.wait_group 0;"  ::: "memory")

// load one 128x64(fp16) tile chunk (16 KB) into SW128-swizzled smem, 256 thr
__device__ __forceinline__ void ld_tile(uint32_t dst, const __half* src,
                                        int ld_elem, size_t kb0, int tid) {
    const char* sb = (const char*)src + kb0;
#pragma unroll
    for (int it = 0; it < 4; ++it) {
        int L = tid * 16 + it * 4096;
        int row = L >> 7, kb = L & 127;
        cp16(dst + (L ^ ((L >> 3) & 0x70)),
             sb + (size_t)row * ((size_t)ld_elem * 2) + kb);
    }
}

// ---------------- fp16 split MMA GEMM core (2-stage) ----------------------------
// C = (Ah [+Al]) * (Bh [+Bl])^T ; products: ah*bh [+ al*bh] [+ ah*bl]
// A 128xK fp16 (lda), B 128xK fp16 (ldb). 8 warps 4(M)x2(N), warp 32x64.
// Epilogue f2(row, col, v0, v1) with (col, col+1) pair, tile-relative.
template <bool SPLIT_A, bool SPLIT_B, class F2>
__device__ __forceinline__ void mma_gemm(
    const __half* __restrict__ Ah, const __half* __restrict__ Al, int lda,
    const __half* __restrict__ Bh, const __half* __restrict__ Bl, int ldb,
    int K, F2 f2)
{
    constexpr uint32_t OFFAL = 16384;
    constexpr uint32_t OFFB  = SPLIT_A ? 32768 : 16384;
    constexpr uint32_t OFFBL = OFFB + 16384;
    constexpr uint32_t STG   = 16384u * (2 + (SPLIT_A ? 1 : 0) + (SPLIT_B ? 1 : 0));
    extern __shared__ char smem[];
    const uint32_t sbase = smem_u32(smem);
    const int tid = threadIdx.x;
    const int lane = tid & 31;
    const int wid = tid >> 5;
    const int wm = wid >> 1, wn = wid & 1;

    float c[2][8][4];
#pragma unroll
    for (int i = 0; i < 2; ++i)
#pragma unroll
        for (int j = 0; j < 8; ++j)
#pragma unroll
            for (int e = 0; e < 4; ++e) c[i][j][e] = 0.f;

    const int NCH = K >> 6;
    const int lhalf = (lane >> 4) << 4;
    const int arow  = wm * 32 + (lane & 15);
    const int brow  = wn * 64 + (lane & 15);

#define LOAD_CHUNK(CC, ST)                                                    \
    {                                                                         \
        uint32_t st_ = sbase + (ST) * STG;                                    \
        size_t kb0_ = (size_t)(CC) * 128;                                     \
        ld_tile(st_, Ah, lda, kb0_, tid);                                     \
        if (SPLIT_A) ld_tile(st_ + OFFAL, Al, lda, kb0_, tid);                \
        ld_tile(st_ + OFFB, Bh, ldb, kb0_, tid);                              \
        if (SPLIT_B) ld_tile(st_ + OFFBL, Bl, ldb, kb0_, tid);                \
    }

    LOAD_CHUNK(0, 0); CP_COMMIT();

    for (int cc = 0; cc < NCH; ++cc) {
        if (cc + 1 < NCH) {
            LOAD_CHUNK(cc + 1, (cc + 1) & 1);
            CP_COMMIT();
            CP_WAIT1();
        } else {
            CP_WAIT0();
        }
        __syncthreads();

        const uint32_t st = sbase + (cc & 1) * STG;
#pragma unroll
        for (int ks = 0; ks < 4; ++ks) {
            const int kb = ks * 32 + lhalf;
            uint32_t ah[2][4], al[2][4];
#pragma unroll
            for (int mt = 0; mt < 2; ++mt) {
                uint32_t off = (uint32_t)(arow + mt * 16) * 128 + kb;
                off ^= (off >> 3) & 0x70;
                ldmx4(ah[mt], st + off);
                if (SPLIT_A) ldmx4(al[mt], st + OFFAL + off);
            }
#pragma unroll
            for (int np = 0; np < 4; ++np) {
                uint32_t off = (uint32_t)(brow + np * 16) * 128 + kb;
                off ^= (off >> 3) & 0x70;
                uint32_t bh[4];
                ldmx4(bh, st + OFFB + off);
                uint32_t bl[4];
                if (SPLIT_B) ldmx4(bl, st + OFFBL + off);
#pragma unroll
                for (int mt = 0; mt < 2; ++mt) {
                    float* c0 = c[mt][np * 2 + 0];
                    float* c1 = c[mt][np * 2 + 1];
                    mma16816(c0, ah[mt], bh[0], bh[2]);
                    mma16816(c1, ah[mt], bh[1], bh[3]);
                    if (SPLIT_A) {
                        mma16816(c0, al[mt], bh[0], bh[2]);
                        mma16816(c1, al[mt], bh[1], bh[3]);
                    }
                    if (SPLIT_B) {
                        mma16816(c0, ah[mt], bl[0], bl[2]);
                        mma16816(c1, ah[mt], bl[1], bl[3]);
                    }
                }
            }
        }
        __syncthreads();
    }
#undef LOAD_CHUNK

    const int gID = lane >> 2, tg = lane & 3;
#pragma unroll
    for (int mt = 0; mt < 2; ++mt)
#pragma unroll
        for (int j = 0; j < 8; ++j) {
            int row = wm * 32 + mt * 16 + gID;
            int col = wn * 64 + j * 8 + tg * 2;
            f2(row,     col, c[mt][j][0], c[mt][j][1]);
            f2(row + 8, col, c[mt][j][2], c[mt][j][3]);
        }
}

// split a fp32 pair into hi/lo half2
__device__ __forceinline__ void split2(float v0, float v1,
                                       __half2& h, __half2& l) {
    h.x = __float2half_rn(v0); h.y = __float2half_rn(v1);
    l.x = __float2half_rn(v0 - __half2float(h.x));
    l.y = __float2half_rn(v1 - __half2float(h.y));
}

// ---------------- LayerNorm -> fp16 hi/lo --------------------------------------
__global__ __launch_bounds__(256) void ln_kernel(const float* __restrict__ x,
                                                 const float* __restrict__ w,
                                                 const float* __restrict__ b)
{
    int row = blockIdx.x;
    int tid = threadIdx.x;
    float4 v = ((const float4*)(x + (size_t)row * DD))[tid];
    float s  = v.x + v.y + v.z + v.w;
    float ss = v.x*v.x + v.y*v.y + v.z*v.z + v.w*v.w;
#pragma unroll
    for (int o = 16; o; o >>= 1) {
        s  += __shfl_xor_sync(0xffffffffu, s , o);
        ss += __shfl_xor_sync(0xffffffffu, ss, o);
    }
    __shared__ float sh_s[8], sh_ss[8];
    int warp = tid >> 5;
    if ((tid & 31) == 0) { sh_s[warp] = s; sh_ss[warp] = ss; }
    __syncthreads();
    if (tid == 0) {
        float ts = 0.f, tss = 0.f;
#pragma unroll
        for (int i = 0; i < 8; ++i) { ts += sh_s[i]; tss += sh_ss[i]; }
        sh_s[0] = ts; sh_ss[0] = tss;
    }
    __syncthreads();
    float mean = sh_s[0] * (1.0f / DD);
    float var  = sh_ss[0] * (1.0f / DD) - mean * mean;
    float rs   = rsqrtf(var + 1e-5f);
    float4 wv = ((const float4*)w)[tid];
    float4 bv = ((const float4*)b)[tid];
    float o0 = (v.x - mean) * rs * wv.x + bv.x;
    float o1 = (v.y - mean) * rs * wv.y + bv.y;
    float o2 = (v.z - mean) * rs * wv.z + bv.z;
    float o3 = (v.w - mean) * rs * wv.w + bv.w;
    size_t eb = (size_t)row * DD + tid * 4;
    __half2 hA, lA, hB, lB;
    split2(o0, o1, hA, lA);
    split2(o2, o3, hB, lB);
    ((__half2*)(g_xnh + eb))[0] = hA;
    ((__half2*)(g_xnh + eb))[1] = hB;
    ((__half2*)(g_xnl + eb))[0] = lA;
    ((__half2*)(g_xnl + eb))[1] = lB;
}

// ---------------- fp32 -> fp16 convert ------------------------------------------
__global__ __launch_bounds__(256) void convert_kernel(const float* __restrict__ s,
                                                      __half* __restrict__ d,
                                                      int n4)
{
    int i = blockIdx.x * blockDim.x + threadIdx.x;
    if (i >= n4) return;
    float4 v = ((const float4*)s)[i];
    __half2 a; a.x = __float2half_rn(v.x); a.y = __float2half_rn(v.y);
    __half2 b; b.x = __float2half_rn(v.z); b.y = __float2half_rn(v.w);
    ((__half2*)d)[2 * i]     = a;
    ((__half2*)d)[2 * i + 1] = b;
}

// ---------------- GEMM1a: u,v cols [0,4096), SINGLE product ---------------------
// epilogue routes: col<E -> u (fp16), E<=col<2E -> V^T (fp16)
__global__ __launch_bounds__(256, 2) void gemm_uv_mma(const float* __restrict__ uv_b)
{
    const int m0 = blockIdx.y * 128, n0 = blockIdx.x * 128;
    mma_gemm<false, false>(g_xnh + (size_t)m0 * DD, (const __half*)0, DD,
                           g_wuv + (size_t)n0 * DD, (const __half*)0, DD, DD,
        [&](int r, int cidx, float v0, float v1) {
            int row = m0 + r, col = n0 + cidx;
            float t0 = v0 + uv_b[col];
            float t1 = v1 + uv_b[col + 1];
            float s0 = t0 / (1.f + expf(-t0));
            float s1 = t1 / (1.f + expf(-t1));
            if (col >= EE) {
                int bt = row >> 9, n = row & (NN - 1);
                int e = col - EE;
                size_t base = ((size_t)bt * EE + e) * NN + n;
                g_vt[base]      = __float2half_rn(s0);
                g_vt[base + NN] = __float2half_rn(s1);
            } else {
                __half2 h;
                h.x = __float2half_rn(s0);
                h.y = __float2half_rn(s1);
                *(__half2*)(g_u + (size_t)row * EE + col) = h;
            }
        });
}

// ---------------- GEMM1b: base cols [4096,4224), 2-product ----------------------
__global__ __launch_bounds__(256, 2) void gemm_base_mma(const float* __restrict__ uv_b)
{
    const int m0 = blockIdx.y * 128;
    mma_gemm<true, false>(g_xnh + (size_t)m0 * DD, g_xnl + (size_t)m0 * DD, DD,
                          g_wuv + (size_t)(2 * EE) * DD, (const __half*)0, DD, DD,
        [&](int r, int cidx, float v0, float v1) {
            int row = m0 + r;
            float t0 = v0 + uv_b[2 * EE + cidx];
            float t1 = v1 + uv_b[2 * EE + cidx + 1];
            float2 o;
            o.x = t0 / (1.f + expf(-t0));
            o.y = t1 / (1.f + expf(-t1));
            *(float2*)(g_base + (size_t)row * SS + cidx) = o;
        });
}

// ---------------- gamma/beta + RoPE -> q, k (fp16 hi/lo) -------------------------
__global__ void rope_kernel(const float* __restrict__ gamma,
                            const float* __restrict__ beta)
{
    const int row = blockIdx.x;
    const int s   = threadIdx.x;       // 0..63
    const int n   = row & (NN - 1);
    const float* base = g_base + (size_t)row * SS;
    const float b1 = base[s];
    const float b2 = base[s + 64];
    const float inv_freq = powf(10000.0f, (float)s * (1.0f / 64.0f));
    const float arg = (float)n * inv_freq;
    const float sn = sinf(arg);
    const float cs = cosf(arg);
#pragma unroll
    for (int h = 0; h < 2; ++h) {
        const float x1 = b1 * gamma[h * SS + s]      + beta[h * SS + s];
        const float x2 = b2 * gamma[h * SS + s + 64] + beta[h * SS + s + 64];
        float q1 = x1 * cs - x2 * sn;
        float q2 = x2 * cs + x1 * sn;
        __half* dh = (h == 0 ? g_qh : g_kh) + (size_t)row * SS;
        __half* dl = (h == 0 ? g_ql : g_kl) + (size_t)row * SS;
        __half h1 = __float2half_rn(q1), h2 = __float2half_rn(q2);
        dh[s]      = h1;
        dh[s + 64] = h2;
        dl[s]      = __float2half_rn(q1 - __half2float(h1));
        dl[s + 64] = __float2half_rn(q2 - __half2float(h2));
    }
}

// ---------------- qk: 3-product split MMA + bias + relu^2 -> ker (single fp16) ---
__global__ __launch_bounds__(256) void qk_mma(const float* __restrict__ w_rel)
{
    const int bt = blockIdx.z;
    const int m0 = blockIdx.y * 128, n0 = blockIdx.x * 128;
    const size_t rbase = (size_t)bt * NN;
    mma_gemm<true, true>(g_qh + (rbase + m0) * SS, g_ql + (rbase + m0) * SS, SS,
                         g_kh + (rbase + n0) * SS, g_kl + (rbase + n0) * SS, SS, SS,
        [&](int r, int cidx, float v0, float v1) {
            int row = m0 + r, col = n0 + cidx;
            float t0 = v0 * (1.0f / 512.0f) + w_rel[col - row + 511];
            float t1 = v1 * (1.0f / 512.0f) + w_rel[col + 1 - row + 511];
            float r0 = fmaxf(t0, 0.f), r1 = fmaxf(t1, 0.f);
            __half2 h;
            h.x = __float2half_rn(r0 * r0);
            h.y = __float2half_rn(r1 * r1);
            *(__half2*)(g_kerh + (rbase + row) * NN + col) = h;
        });
}

// ---------------- kv: g = (ker @ V) * u  (single product) ------------------------
__global__ __launch_bounds__(256, 2) void kv_mma()
{
    const int bt = blockIdx.z;
    const int m0 = blockIdx.y * 128, n0 = blockIdx.x * 128;
    const size_t rbase = (size_t)bt * NN;
    mma_gemm<false, false>(g_kerh + (rbase + m0) * NN, (const __half*)0, NN,
                           g_vt + ((size_t)bt * EE + n0) * NN, (const __half*)0, NN, NN,
        [&](int r, int cidx, float v0, float v1) {
            size_t grow = rbase + m0 + r;
            int col = n0 + cidx;
            __half2 u2 = *(const __half2*)(g_u + grow * EE + col);
            __half2 h;
            h.x = __float2half_rn(__half2float(u2.x) * v0);
            h.y = __float2half_rn(__half2float(u2.y) * v1);
            *(__half2*)(g_gh + grow * EE + col) = h;
        });
}

// ---------------- out = g @ o_w^T + o_b + shortcut (single product) ---------------
__global__ __launch_bounds__(256, 2) void out_mma(const float* __restrict__ o_b,
                                                  const float* __restrict__ x,
                                                  float* __restrict__ out)
{
    const int m0 = blockIdx.y * 128, n0 = blockIdx.x * 128;
    mma_gemm<false, false>(g_gh + (size_t)m0 * EE, (const __half*)0, EE,
                           g_ow + (size_t)n0 * EE, (const __half*)0, EE, EE,
        [&](int r, int cidx, float v0, float v1) {
            int row = m0 + r, col = n0 + cidx;
            float2 xr = *(const float2*)(x + (size_t)row * DD + col);
            float2 o;
            o.x = v0 + o_b[col]     + xr.x;
            o.y = v1 + o_b[col + 1] + xr.y;
            *(float2*)(out + (size_t)row * DD + col) = o;
        });
}

// ---------------- launch ------------------------------------------------------------
#define SMEM_UV   (2 * 32768)   // single product: A|B
#define SMEM_BASE (2 * 49152)   // A-split: AH|AL|B
#define SMEM_QK   (2 * 65536)   // both split
#define SMEM_KV   (2 * 32768)
#define SMEM_OUT  (2 * 32768)

extern "C" void kernel_launch(void* const* d_in, const int* in_sizes, int n_in,
                              void* d_out, int out_size)
{
    const float* x     = (const float*)d_in[0];
    const float* ln_w  = (const float*)d_in[1];
    const float* ln_b  = (const float*)d_in[2];
    const float* uv_w  = (const float*)d_in[3];
    const float* uv_b  = (const float*)d_in[4];
    const float* gamma = (const float*)d_in[5];
    const float* beta  = (const float*)d_in[6];
    const float* o_w   = (const float*)d_in[7];
    const float* o_b   = (const float*)d_in[8];
    const float* w_rel = (const float*)d_in[9];
    float* out = (float*)d_out;

    cudaFuncSetAttribute(gemm_uv_mma,   cudaFuncAttributeMaxDynamicSharedMemorySize, SMEM_UV);
    cudaFuncSetAttribute(gemm_base_mma, cudaFuncAttributeMaxDynamicSharedMemorySize, SMEM_BASE);
    cudaFuncSetAttribute(kv_mma,        cudaFuncAttributeMaxDynamicSharedMemorySize, SMEM_KV);
    cudaFuncSetAttribute(out_mma,       cudaFuncAttributeMaxDynamicSharedMemorySize, SMEM_OUT);
    cudaFuncSetAttribute(qk_mma,        cudaFuncAttributeMaxDynamicSharedMemorySize, SMEM_QK);

    __half *wuv, *ow;
    cudaGetSymbolAddress((void**)&wuv, g_wuv);
    cudaGetSymbolAddress((void**)&ow,  g_ow);

    ln_kernel<<<MTOT, 256>>>(x, ln_w, ln_b);
    convert_kernel<<<(FF * DD / 4 + 255) / 256, 256>>>(uv_w, wuv, FF * DD / 4);
    convert_kernel<<<(DD * EE / 4 + 255) / 256, 256>>>(o_w, ow, DD * EE / 4);
    gemm_base_mma<<<dim3(1,          MTOT / 128), 256, SMEM_BASE>>>(uv_b);
    rope_kernel<<<MTOT, 64>>>(gamma, beta);
    gemm_uv_mma  <<<dim3(4096 / 128, MTOT / 128), 256, SMEM_UV>>>(uv_b);
    qk_mma<<<dim3(NN / 128, NN / 128, BB), 256, SMEM_QK>>>(w_rel);
    kv_mma<<<dim3(EE / 128, NN / 128, BB), 256, SMEM_KV>>>();
    out_mma<<<dim3(DD / 128, MTOT / 128), 256, SMEM_OUT>>>(o_b, x, out);
}

// round 15
// speedup vs baseline: 1.1301x; 1.0713x over previous
#include <cuda_runtime.h>
#include <cuda_fp16.h>
#include <math.h>
#include <stdint.h>

#define BB     16
#define NN     512
#define DD     1024
#define EE     2048
#define SS     128
#define FF     4224
#define MTOT   8192

// ---------------- scratch ----------------------------------------------------
__device__ __half g_xnh[(size_t)MTOT * DD];
__device__ __half g_xnl[(size_t)MTOT * DD];
__device__ __half g_wuv[(size_t)FF * DD];
__device__ __half g_u  [(size_t)MTOT * EE];      // u gate, fp16
__device__ float  g_base[(size_t)MTOT * SS];     // base (pre-RoPE), fp32 dense
__device__ __half g_vt [(size_t)BB * EE * NN];   // V^T fp16
__device__ __half g_qh [(size_t)MTOT * SS];
__device__ __half g_ql [(size_t)MTOT * SS];
__device__ __half g_kh [(size_t)MTOT * SS];
__device__ __half g_kl [(size_t)MTOT * SS];
__device__ __half g_kerh[(size_t)BB * NN * NN];  // ker single fp16
__device__ __half g_gh [(size_t)MTOT * EE];
__device__ __half g_ow [(size_t)DD * EE];

// ---------------- helpers -----------------------------------------------------
__device__ __forceinline__ uint32_t smem_u32(const void* p) {
    uint32_t a;
    asm("{ .reg .u64 t; cvta.to.shared.u64 t, %1; cvt.u32.u64 %0, t; }" : "=r"(a) : "l"(p));
    return a;
}
__device__ __forceinline__ void ldmx4(uint32_t* r, uint32_t a) {
    asm volatile("ldmatrix.sync.aligned.m8n8.x4.shared.b16 {%0,%1,%2,%3}, [%4];"
        : "=r"(r[0]), "=r"(r[1]), "=r"(r[2]), "=r"(r[3]) : "r"(a));
}
__device__ __forceinline__ void mma16816(float* c, const uint32_t* a,
                                         uint32_t b0, uint32_t b1) {
    asm volatile("mma.sync.aligned.m16n8k16.row.col.f32.f16.f16.f32 "
        "{%0,%1,%2,%3}, {%4,%5,%6,%7}, {%8,%9}, {%0,%1,%2,%3};"
        : "+f"(c[0]), "+f"(c[1]), "+f"(c[2]), "+f"(c[3])
        : "r"(a[0]), "r"(a[1]), "r"(a[2]), "r"(a[3]), "r"(b0), "r"(b1));
}
__device__ __forceinline__ void cp16(uint32_t dst, const void* src) {
    asm volatile("cp.async.cg.shared.global [%0], [%1], 16;" :: "r"(dst), "l"(src) : "memory");
}
#define CP_COMMIT() asm volatile("cp.async.commit_group;" ::: "memory")
#define CP_WAIT1()  asm volatile("cp.async.wait_group 1;"  ::: "memory")
#define CP_WAIT0()  asm volatile("cp.async.wait_group 0;"  ::: "memory")

// load one 128x64(fp16) tile chunk (16 KB) into SW128-swizzled smem, 256 thr
__device__ __forceinline__ void ld_tile(uint32_t dst, const __half* src,
                                        int ld_elem, size_t kb0, int tid) {
    const char* sb = (const char*)src + kb0;
#pragma unroll
    for (int it = 0; it < 4; ++it) {
        int L = tid * 16 + it * 4096;
        int row = L >> 7, kb = L & 127;
        cp16(dst + (L ^ ((L >> 3) & 0x70)),
             sb + (size_t)row * ((size_t)ld_elem * 2) + kb);
    }
}

// ---------------- fp16 split MMA GEMM core (2-stage) ----------------------------
template <bool SPLIT_A, bool SPLIT_B, class F2>
__device__ __forceinline__ void mma_gemm(
    const __half* __restrict__ Ah, const __half* __restrict__ Al, int lda,
    const __half* __restrict__ Bh, const __half* __restrict__ Bl, int ldb,
    int K, F2 f2)
{
    constexpr uint32_t OFFAL = 16384;
    constexpr uint32_t OFFB  = SPLIT_A ? 32768 : 16384;
    constexpr uint32_t OFFBL = OFFB + 16384;
    constexpr uint32_t STG   = 16384u * (2 + (SPLIT_A ? 1 : 0) + (SPLIT_B ? 1 : 0));
    extern __shared__ char smem[];
    const uint32_t sbase = smem_u32(smem);
    const int tid = threadIdx.x;
    const int lane = tid & 31;
    const int wid = tid >> 5;
    const int wm = wid >> 1, wn = wid & 1;

    float c[2][8][4];
#pragma unroll
    for (int i = 0; i < 2; ++i)
#pragma unroll
        for (int j = 0; j < 8; ++j)
#pragma unroll
            for (int e = 0; e < 4; ++e) c[i][j][e] = 0.f;

    const int NCH = K >> 6;
    const int lhalf = (lane >> 4) << 4;
    const int arow  = wm * 32 + (lane & 15);
    const int brow  = wn * 64 + (lane & 15);

#define LOAD_CHUNK(CC, ST)                                                    \
    {                                                                         \
        uint32_t st_ = sbase + (ST) * STG;                                    \
        size_t kb0_ = (size_t)(CC) * 128;                                     \
        ld_tile(st_, Ah, lda, kb0_, tid);                                     \
        if (SPLIT_A) ld_tile(st_ + OFFAL, Al, lda, kb0_, tid);                \
        ld_tile(st_ + OFFB, Bh, ldb, kb0_, tid);                              \
        if (SPLIT_B) ld_tile(st_ + OFFBL, Bl, ldb, kb0_, tid);                \
    }

    LOAD_CHUNK(0, 0); CP_COMMIT();

    for (int cc = 0; cc < NCH; ++cc) {
        if (cc + 1 < NCH) {
            LOAD_CHUNK(cc + 1, (cc + 1) & 1);
            CP_COMMIT();
            CP_WAIT1();
        } else {
            CP_WAIT0();
        }
        __syncthreads();

        const uint32_t st = sbase + (cc & 1) * STG;
#pragma unroll
        for (int ks = 0; ks < 4; ++ks) {
            const int kb = ks * 32 + lhalf;
            uint32_t ah[2][4], al[2][4];
#pragma unroll
            for (int mt = 0; mt < 2; ++mt) {
                uint32_t off = (uint32_t)(arow + mt * 16) * 128 + kb;
                off ^= (off >> 3) & 0x70;
                ldmx4(ah[mt], st + off);
                if (SPLIT_A) ldmx4(al[mt], st + OFFAL + off);
            }
#pragma unroll
            for (int np = 0; np < 4; ++np) {
                uint32_t off = (uint32_t)(brow + np * 16) * 128 + kb;
                off ^= (off >> 3) & 0x70;
                uint32_t bh[4];
                ldmx4(bh, st + OFFB + off);
                uint32_t bl[4];
                if (SPLIT_B) ldmx4(bl, st + OFFBL + off);
#pragma unroll
                for (int mt = 0; mt < 2; ++mt) {
                    float* c0 = c[mt][np * 2 + 0];
                    float* c1 = c[mt][np * 2 + 1];
                    mma16816(c0, ah[mt], bh[0], bh[2]);
                    mma16816(c1, ah[mt], bh[1], bh[3]);
                    if (SPLIT_A) {
                        mma16816(c0, al[mt], bh[0], bh[2]);
                        mma16816(c1, al[mt], bh[1], bh[3]);
                    }
                    if (SPLIT_B) {
                        mma16816(c0, ah[mt], bl[0], bl[2]);
                        mma16816(c1, ah[mt], bl[1], bl[3]);
                    }
                }
            }
        }
        __syncthreads();
    }
#undef LOAD_CHUNK

    const int gID = lane >> 2, tg = lane & 3;
#pragma unroll
    for (int mt = 0; mt < 2; ++mt)
#pragma unroll
        for (int j = 0; j < 8; ++j) {
            int row = wm * 32 + mt * 16 + gID;
            int col = wn * 64 + j * 8 + tg * 2;
            f2(row,     col, c[mt][j][0], c[mt][j][1]);
            f2(row + 8, col, c[mt][j][2], c[mt][j][3]);
        }
}

// split a fp32 pair into hi/lo half2
__device__ __forceinline__ void split2(float v0, float v1,
                                       __half2& h, __half2& l) {
    h.x = __float2half_rn(v0); h.y = __float2half_rn(v1);
    l.x = __float2half_rn(v0 - __half2float(h.x));
    l.y = __float2half_rn(v1 - __half2float(h.y));
}

// ---------------- LayerNorm -> fp16 hi/lo --------------------------------------
__global__ __launch_bounds__(256) void ln_kernel(const float* __restrict__ x,
                                                 const float* __restrict__ w,
                                                 const float* __restrict__ b)
{
    int row = blockIdx.x;
    int tid = threadIdx.x;
    float4 v = ((const float4*)(x + (size_t)row * DD))[tid];
    float s  = v.x + v.y + v.z + v.w;
    float ss = v.x*v.x + v.y*v.y + v.z*v.z + v.w*v.w;
#pragma unroll
    for (int o = 16; o; o >>= 1) {
        s  += __shfl_xor_sync(0xffffffffu, s , o);
        ss += __shfl_xor_sync(0xffffffffu, ss, o);
    }
    __shared__ float sh_s[8], sh_ss[8];
    int warp = tid >> 5;
    if ((tid & 31) == 0) { sh_s[warp] = s; sh_ss[warp] = ss; }
    __syncthreads();
    if (tid == 0) {
        float ts = 0.f, tss = 0.f;
#pragma unroll
        for (int i = 0; i < 8; ++i) { ts += sh_s[i]; tss += sh_ss[i]; }
        sh_s[0] = ts; sh_ss[0] = tss;
    }
    __syncthreads();
    float mean = sh_s[0] * (1.0f / DD);
    float var  = sh_ss[0] * (1.0f / DD) - mean * mean;
    float rs   = rsqrtf(var + 1e-5f);
    float4 wv = ((const float4*)w)[tid];
    float4 bv = ((const float4*)b)[tid];
    float o0 = (v.x - mean) * rs * wv.x + bv.x;
    float o1 = (v.y - mean) * rs * wv.y + bv.y;
    float o2 = (v.z - mean) * rs * wv.z + bv.z;
    float o3 = (v.w - mean) * rs * wv.w + bv.w;
    size_t eb = (size_t)row * DD + tid * 4;
    __half2 hA, lA, hB, lB;
    split2(o0, o1, hA, lA);
    split2(o2, o3, hB, lB);
    ((__half2*)(g_xnh + eb))[0] = hA;
    ((__half2*)(g_xnh + eb))[1] = hB;
    ((__half2*)(g_xnl + eb))[0] = lA;
    ((__half2*)(g_xnl + eb))[1] = lB;
}

// ---------------- fp32 -> fp16 convert ------------------------------------------
__global__ __launch_bounds__(256) void convert_kernel(const float* __restrict__ s,
                                                      __half* __restrict__ d,
                                                      int n4)
{
    int i = blockIdx.x * blockDim.x + threadIdx.x;
    if (i >= n4) return;
    float4 v = ((const float4*)s)[i];
    __half2 a; a.x = __float2half_rn(v.x); a.y = __float2half_rn(v.y);
    __half2 b; b.x = __float2half_rn(v.z); b.y = __float2half_rn(v.w);
    ((__half2*)d)[2 * i]     = a;
    ((__half2*)d)[2 * i + 1] = b;
}

// ---------------- GEMM1a: u,v cols [0,4096), SINGLE product ---------------------
__global__ __launch_bounds__(256, 2) void gemm_uv_mma(const float* __restrict__ uv_b)
{
    const int m0 = blockIdx.y * 128, n0 = blockIdx.x * 128;
    mma_gemm<false, false>(g_xnh + (size_t)m0 * DD, (const __half*)0, DD,
                           g_wuv + (size_t)n0 * DD, (const __half*)0, DD, DD,
        [&](int r, int cidx, float v0, float v1) {
            int row = m0 + r, col = n0 + cidx;
            float t0 = v0 + uv_b[col];
            float t1 = v1 + uv_b[col + 1];
            float s0 = t0 / (1.f + expf(-t0));
            float s1 = t1 / (1.f + expf(-t1));
            if (col >= EE) {
                int bt = row >> 9, n = row & (NN - 1);
                int e = col - EE;
                size_t base = ((size_t)bt * EE + e) * NN + n;
                g_vt[base]      = __float2half_rn(s0);
                g_vt[base + NN] = __float2half_rn(s1);
            } else {
                __half2 h;
                h.x = __float2half_rn(s0);
                h.y = __float2half_rn(s1);
                *(__half2*)(g_u + (size_t)row * EE + col) = h;
            }
        });
}

// ---------------- GEMM1b: base cols [4096,4224), 2-product ----------------------
__global__ __launch_bounds__(256, 2) void gemm_base_mma(const float* __restrict__ uv_b)
{
    const int m0 = blockIdx.y * 128;
    mma_gemm<true, false>(g_xnh + (size_t)m0 * DD, g_xnl + (size_t)m0 * DD, DD,
                          g_wuv + (size_t)(2 * EE) * DD, (const __half*)0, DD, DD,
        [&](int r, int cidx, float v0, float v1) {
            int row = m0 + r;
            float t0 = v0 + uv_b[2 * EE + cidx];
            float t1 = v1 + uv_b[2 * EE + cidx + 1];
            float2 o;
            o.x = t0 / (1.f + expf(-t0));
            o.y = t1 / (1.f + expf(-t1));
            *(float2*)(g_base + (size_t)row * SS + cidx) = o;
        });
}

// ---------------- gamma/beta + RoPE -> q, k (fp16 hi/lo) -------------------------
__global__ void rope_kernel(const float* __restrict__ gamma,
                            const float* __restrict__ beta)
{
    const int row = blockIdx.x;
    const int s   = threadIdx.x;       // 0..63
    const int n   = row & (NN - 1);
    const float* base = g_base + (size_t)row * SS;
    const float b1 = base[s];
    const float b2 = base[s + 64];
    const float inv_freq = powf(10000.0f, (float)s * (1.0f / 64.0f));
    const float arg = (float)n * inv_freq;
    const float sn = sinf(arg);
    const float cs = cosf(arg);
#pragma unroll
    for (int h = 0; h < 2; ++h) {
        const float x1 = b1 * gamma[h * SS + s]      + beta[h * SS + s];
        const float x2 = b2 * gamma[h * SS + s + 64] + beta[h * SS + s + 64];
        float q1 = x1 * cs - x2 * sn;
        float q2 = x2 * cs + x1 * sn;
        __half* dh = (h == 0 ? g_qh : g_kh) + (size_t)row * SS;
        __half* dl = (h == 0 ? g_ql : g_kl) + (size_t)row * SS;
        __half h1 = __float2half_rn(q1), h2 = __float2half_rn(q2);
        dh[s]      = h1;
        dh[s + 64] = h2;
        dl[s]      = __float2half_rn(q1 - __half2float(h1));
        dl[s + 64] = __float2half_rn(q2 - __half2float(h2));
    }
}

// ---------------- qk: 3-product split MMA + bias + relu^2 -> ker (single fp16) ---
__global__ __launch_bounds__(256) void qk_mma(const float* __restrict__ w_rel)
{
    const int bt = blockIdx.z;
    const int m0 = blockIdx.y * 128, n0 = blockIdx.x * 128;
    const size_t rbase = (size_t)bt * NN;
    mma_gemm<true, true>(g_qh + (rbase + m0) * SS, g_ql + (rbase + m0) * SS, SS,
                         g_kh + (rbase + n0) * SS, g_kl + (rbase + n0) * SS, SS, SS,
        [&](int r, int cidx, float v0, float v1) {
            int row = m0 + r, col = n0 + cidx;
            float t0 = v0 * (1.0f / 512.0f) + w_rel[col - row + 511];
            float t1 = v1 * (1.0f / 512.0f) + w_rel[col + 1 - row + 511];
            float r0 = fmaxf(t0, 0.f), r1 = fmaxf(t1, 0.f);
            __half2 h;
            h.x = __float2half_rn(r0 * r0);
            h.y = __float2half_rn(r1 * r1);
            *(__half2*)(g_kerh + (rbase + row) * NN + col) = h;
        });
}

// ---------------- kv: g = (ker @ V) * u  (single product) ------------------------
__global__ __launch_bounds__(256, 2) void kv_mma()
{
    const int bt = blockIdx.z;
    const int m0 = blockIdx.y * 128, n0 = blockIdx.x * 128;
    const size_t rbase = (size_t)bt * NN;
    mma_gemm<false, false>(g_kerh + (rbase + m0) * NN, (const __half*)0, NN,
                           g_vt + ((size_t)bt * EE + n0) * NN, (const __half*)0, NN, NN,
        [&](int r, int cidx, float v0, float v1) {
            size_t grow = rbase + m0 + r;
            int col = n0 + cidx;
            __half2 u2 = *(const __half2*)(g_u + grow * EE + col);
            __half2 h;
            h.x = __float2half_rn(__half2float(u2.x) * v0);
            h.y = __float2half_rn(__half2float(u2.y) * v1);
            *(__half2*)(g_gh + grow * EE + col) = h;
        });
}

// ---------------- out = g @ o_w^T + o_b + shortcut (single product) ---------------
__global__ __launch_bounds__(256, 2) void out_mma(const float* __restrict__ o_b,
                                                  const float* __restrict__ x,
                                                  float* __restrict__ out)
{
    const int m0 = blockIdx.y * 128, n0 = blockIdx.x * 128;
    mma_gemm<false, false>(g_gh + (size_t)m0 * EE, (const __half*)0, EE,
                           g_ow + (size_t)n0 * EE, (const __half*)0, EE, EE,
        [&](int r, int cidx, float v0, float v1) {
            int row = m0 + r, col = n0 + cidx;
            float2 xr = *(const float2*)(x + (size_t)row * DD + col);
            float2 o;
            o.x = v0 + o_b[col]     + xr.x;
            o.y = v1 + o_b[col + 1] + xr.y;
            *(float2*)(out + (size_t)row * DD + col) = o;
        });
}

// ---------------- launch ------------------------------------------------------------
#define SMEM_UV   (2 * 32768)
#define SMEM_BASE (2 * 49152)
#define SMEM_QK   (2 * 65536)
#define SMEM_KV   (2 * 32768)
#define SMEM_OUT  (2 * 32768)

extern "C" void kernel_launch(void* const* d_in, const int* in_sizes, int n_in,
                              void* d_out, int out_size)
{
    const float* x     = (const float*)d_in[0];
    const float* ln_w  = (const float*)d_in[1];
    const float* ln_b  = (const float*)d_in[2];
    const float* uv_w  = (const float*)d_in[3];
    const float* uv_b  = (const float*)d_in[4];
    const float* gamma = (const float*)d_in[5];
    const float* beta  = (const float*)d_in[6];
    const float* o_w   = (const float*)d_in[7];
    const float* o_b   = (const float*)d_in[8];
    const float* w_rel = (const float*)d_in[9];
    float* out = (float*)d_out;

    cudaFuncSetAttribute(gemm_uv_mma,   cudaFuncAttributeMaxDynamicSharedMemorySize, SMEM_UV);
    cudaFuncSetAttribute(gemm_base_mma, cudaFuncAttributeMaxDynamicSharedMemorySize, SMEM_BASE);
    cudaFuncSetAttribute(kv_mma,        cudaFuncAttributeMaxDynamicSharedMemorySize, SMEM_KV);
    cudaFuncSetAttribute(out_mma,       cudaFuncAttributeMaxDynamicSharedMemorySize, SMEM_OUT);
    cudaFuncSetAttribute(qk_mma,        cudaFuncAttributeMaxDynamicSharedMemorySize, SMEM_QK);

    __half *wuv, *ow;
    cudaGetSymbolAddress((void**)&wuv, g_wuv);
    cudaGetSymbolAddress((void**)&ow,  g_ow);

    // one-time host objects (not device memory): side stream + fork/join events
    static cudaStream_t s1 = [] {
        cudaStream_t s;
        cudaStreamCreateWithFlags(&s, cudaStreamNonBlocking);
        return s;
    }();
    static cudaEvent_t evFork = [] {
        cudaEvent_t e;
        cudaEventCreateWithFlags(&e, cudaEventDisableTiming);
        return e;
    }();
    static cudaEvent_t evJoin = [] {
        cudaEvent_t e;
        cudaEventCreateWithFlags(&e, cudaEventDisableTiming);
        return e;
    }();

    // common prologue on the capture (default) stream
    ln_kernel<<<MTOT, 256>>>(x, ln_w, ln_b);
    convert_kernel<<<(FF * DD / 4 + 255) / 256, 256>>>(uv_w, wuv, FF * DD / 4);

    // fork: arm B (base -> rope -> qk, + o_w convert) on side stream
    cudaEventRecord(evFork, 0);
    cudaStreamWaitEvent(s1, evFork, 0);
    gemm_base_mma<<<dim3(1, MTOT / 128), 256, SMEM_BASE, s1>>>(uv_b);
    rope_kernel<<<MTOT, 64, 0, s1>>>(gamma, beta);
    qk_mma<<<dim3(NN / 128, NN / 128, BB), 256, SMEM_QK, s1>>>(w_rel);
    convert_kernel<<<(DD * EE / 4 + 255) / 256, 256, 0, s1>>>(o_w, ow, DD * EE / 4);
    cudaEventRecord(evJoin, s1);

    // arm A (wide uv GEMM) on the default stream, overlapping arm B
    gemm_uv_mma<<<dim3(4096 / 128, MTOT / 128), 256, SMEM_UV>>>(uv_b);

    // join, then the dependent tail
    cudaStreamWaitEvent(0, evJoin, 0);
    kv_mma<<<dim3(EE / 128, NN / 128, BB), 256, SMEM_KV>>>();
    out_mma<<<dim3(DD / 128, MTOT / 128), 256, SMEM_OUT>>>(o_b, x, out);
}